// round 8
// baseline (speedup 1.0000x reference)
#include <cuda_runtime.h>
#include <cuda_fp16.h>
#include <math.h>
#include <stdint.h>

// Problem constants
#define BATCH   4096
#define INDIM   512
#define LATENT  512
#define NHEAD   8
#define DHEAD   64
#define KVBN    1032            // H*(2D+1) = 8*129
#define LN_EPS  1e-5f
#define NCHUNK  4
#define CROWS   (BATCH / NCHUNK)   // 1024 rows per pipeline chunk

// ---------------- scratch (device globals; no runtime alloc allowed) ----------------
__device__ __half g_xh   [BATCH * INDIM];
__device__ __half g_ipwh [INDIM * LATENT];
__device__ __half g_mgwh [1024 * LATENT];
__device__ __half g_kvbwh[LATENT * KVBN];
__device__ float  g_h1   [BATCH * LATENT];   // GEMM1 out (fp32, pre-LN)
__device__ __half g_hcath[BATCH * 1024];     // [LN(h) | z] fp16
__device__ __half g_h2h  [BATCH * LATENT];   // GEMM2 out fp16
__device__ float  g_kvb  [BATCH * KVBN];     // GEMM3 out fp32

__device__ __forceinline__ uint32_t smem_u32(const void* p) {
    return (uint32_t)__cvta_generic_to_shared(p);
}
__device__ __forceinline__ void cp_async16(uint32_t dst, const void* src) {
    asm volatile("cp.async.cg.shared.global [%0], [%1], 16;\n" :: "r"(dst), "l"(src));
}
__device__ __forceinline__ void cp_commit() { asm volatile("cp.async.commit_group;\n"); }
__device__ __forceinline__ void cp_wait1()  { asm volatile("cp.async.wait_group 1;\n"); }

__device__ __forceinline__ void ldsm_x4(uint32_t& r0, uint32_t& r1, uint32_t& r2, uint32_t& r3, uint32_t addr) {
    asm volatile("ldmatrix.sync.aligned.m8n8.x4.shared.b16 {%0,%1,%2,%3}, [%4];"
                 : "=r"(r0), "=r"(r1), "=r"(r2), "=r"(r3) : "r"(addr));
}
__device__ __forceinline__ void ldsm_x4_t(uint32_t& r0, uint32_t& r1, uint32_t& r2, uint32_t& r3, uint32_t addr) {
    asm volatile("ldmatrix.sync.aligned.m8n8.x4.trans.shared.b16 {%0,%1,%2,%3}, [%4];"
                 : "=r"(r0), "=r"(r1), "=r"(r2), "=r"(r3) : "r"(addr));
}

// ---------------- fused f32 -> f16 conversion pre-pass (one launch) ----------------
__global__ __launch_bounds__(256) void cvt_half_kernel(
    const float2* __restrict__ s0, __half2* __restrict__ d0, int n0,
    const float2* __restrict__ s1, __half2* __restrict__ d1, int n1,
    const float2* __restrict__ s2, __half2* __restrict__ d2, int n2,
    const float2* __restrict__ s3, __half2* __restrict__ d3, int n3)
{
    const int t = blockIdx.x * 256 + threadIdx.x;
    const int stride = gridDim.x * 256;
    for (int i = t; i < n0; i += stride) d0[i] = __float22half2_rn(s0[i]);
    for (int i = t; i < n1; i += stride) d1[i] = __float22half2_rn(s1[i]);
    for (int i = t; i < n2; i += stride) d2[i] = __float22half2_rn(s2[i]);
    for (int i = t; i < n3; i += stride) d3[i] = __float22half2_rn(s3[i]);
}

// ---------------- fp16 tensor-core GEMM: C = A(MxK) * B(KxN) + bias ----------------
// BM=128, BN=64, BK=32, 128 threads (4 warps: 2 along M x 2 along N), warp tile 64x32.
// m16n8k16 f16 mma, f32 accumulate. 3-stage cp.async ring, ldmatrix fragment loads.
#define HGBM 128
#define HGBN 64
#define HGBK 32
#define SAH  40
#define SBH  72
#define NST  3

template<bool NB, typename OutT>
__global__ __launch_bounds__(128, 4) void h_gemm(
    int M, int N, int K,
    const __half* __restrict__ A, int lda,
    const __half* __restrict__ B, int ldb,
    const float* __restrict__ bias,
    OutT* __restrict__ C, int ldc)
{
    __shared__ __half As[NST][HGBM][SAH];
    __shared__ __half Bs[NST][HGBK][SBH];

    const int tid  = threadIdx.x;
    const int wid  = tid >> 5;
    const int lane = tid & 31;
    const int grp  = lane >> 2;
    const int tig  = lane & 3;
    const int warp_m = (wid & 1) * 64;
    const int warp_n = (wid >> 1) * 32;
    const int block_row = blockIdx.y * HGBM;
    const int block_col = blockIdx.x * HGBN;

    float acc[4][4][4];
    #pragma unroll
    for (int a = 0; a < 4; a++)
        #pragma unroll
        for (int b = 0; b < 4; b++)
            #pragma unroll
            for (int c = 0; c < 4; c++) acc[a][b][c] = 0.f;

    const int KT = K / HGBK;

    auto load_stage = [&](int s, int kt) {
        const int k0 = kt * HGBK;
        #pragma unroll
        for (int i = 0; i < 4; i++) {
            int idx = tid + 128 * i;
            int r = idx >> 2;
            int j = (idx & 3) * 8;
            cp_async16(smem_u32(&As[s][r][j]),
                       A + (size_t)(block_row + r) * lda + k0 + j);
        }
        #pragma unroll
        for (int i = 0; i < 2; i++) {
            int idx = tid + 128 * i;
            int kk = idx >> 3;
            int c8 = (idx & 7) * 8;
            if (!NB || (block_col + c8) < N) {
                cp_async16(smem_u32(&Bs[s][kk][c8]),
                           B + (size_t)(k0 + kk) * ldb + block_col + c8);
            }
        }
    };

    load_stage(0, 0); cp_commit();
    load_stage(1, 1); cp_commit();

    const int a_row = warp_m + (lane & 15);
    const int a_k8  = (lane >> 4) << 3;
    const int b_r16 = (lane & 15);
    const int b_n8  = (lane >> 4) << 3;

    for (int kt = 0; kt < KT; kt++) {
        cp_wait1();
        __syncthreads();
        if (kt + 2 < KT) load_stage((kt + 2) % NST, kt + 2);
        cp_commit();

        const int s = kt % NST;
        #pragma unroll
        for (int ks = 0; ks < 2; ks++) {
            const int k0 = ks * 16;
            uint32_t a[4][4];
            #pragma unroll
            for (int mt = 0; mt < 4; mt++) {
                uint32_t addr = smem_u32(&As[s][a_row + mt * 16][k0 + a_k8]);
                ldsm_x4(a[mt][0], a[mt][1], a[mt][2], a[mt][3], addr);
            }
            uint32_t b[2][4];
            #pragma unroll
            for (int bt = 0; bt < 2; bt++) {
                uint32_t addr = smem_u32(&Bs[s][k0 + b_r16][warp_n + bt * 16 + b_n8]);
                ldsm_x4_t(b[bt][0], b[bt][1], b[bt][2], b[bt][3], addr);
            }
            #pragma unroll
            for (int mt = 0; mt < 4; mt++)
                #pragma unroll
                for (int nt = 0; nt < 4; nt++) {
                    const int bt = nt >> 1;
                    const int hp = (nt & 1) * 2;
                    asm volatile(
                        "mma.sync.aligned.m16n8k16.row.col.f32.f16.f16.f32 "
                        "{%0,%1,%2,%3}, {%4,%5,%6,%7}, {%8,%9}, {%0,%1,%2,%3};\n"
                        : "+f"(acc[mt][nt][0]), "+f"(acc[mt][nt][1]),
                          "+f"(acc[mt][nt][2]), "+f"(acc[mt][nt][3])
                        : "r"(a[mt][0]), "r"(a[mt][1]), "r"(a[mt][2]), "r"(a[mt][3]),
                          "r"(b[bt][hp]), "r"(b[bt][hp + 1]));
                }
        }
    }

    #pragma unroll
    for (int mt = 0; mt < 4; mt++) {
        int r0 = block_row + warp_m + mt * 16 + grp;
        #pragma unroll
        for (int nt = 0; nt < 4; nt++) {
            int c = block_col + warp_n + nt * 8 + tig * 2;
            if (!NB || c < N) {
                float b0 = bias[c], b1 = bias[c + 1];
                float o00 = acc[mt][nt][0] + b0, o01 = acc[mt][nt][1] + b1;
                float o10 = acc[mt][nt][2] + b0, o11 = acc[mt][nt][3] + b1;
                if (sizeof(OutT) == 4) {
                    *(float2*)((float*)C + (size_t)r0 * ldc + c)       = make_float2(o00, o01);
                    *(float2*)((float*)C + (size_t)(r0 + 8) * ldc + c) = make_float2(o10, o11);
                } else {
                    *(__half2*)((__half*)C + (size_t)r0 * ldc + c)       = __floats2half2_rn(o00, o01);
                    *(__half2*)((__half*)C + (size_t)(r0 + 8) * ldc + c) = __floats2half2_rn(o10, o11);
                }
            }
        }
    }
}

// ---------------- LayerNorm (512) on g_h1 chunk -> g_hcath (fp16) + z concat ----------------
__global__ __launch_bounds__(256) void ln_concat_kernel(
    const float* __restrict__ z, const float* __restrict__ gamma,
    const float* __restrict__ beta, int row0)
{
    const int b = blockIdx.x + row0;
    const float* row = g_h1 + (size_t)b * LATENT;
    const float* zr  = z + (size_t)b * LATENT;
    __half* oh = g_hcath + (size_t)b * 1024;
    const int tid = threadIdx.x;

    float v0 = row[tid];
    float v1 = row[tid + 256];

    __shared__ float red[256];
    red[tid] = v0 + v1;
    __syncthreads();
    #pragma unroll
    for (int s = 128; s > 0; s >>= 1) {
        if (tid < s) red[tid] += red[tid + s];
        __syncthreads();
    }
    const float mu = red[0] * (1.f / 512.f);
    __syncthreads();

    float d0 = v0 - mu, d1 = v1 - mu;
    red[tid] = d0 * d0 + d1 * d1;
    __syncthreads();
    #pragma unroll
    for (int s = 128; s > 0; s >>= 1) {
        if (tid < s) red[tid] += red[tid + s];
        __syncthreads();
    }
    const float var = red[0] * (1.f / 512.f);
    const float inv = rsqrtf(var + LN_EPS);

    oh[tid]       = __float2half(d0 * inv * gamma[tid]       + beta[tid]);
    oh[tid + 256] = __float2half(d1 * inv * gamma[tid + 256] + beta[tid + 256]);
    oh[512 + tid]       = __float2half(zr[tid]);
    oh[512 + tid + 256] = __float2half(zr[tid + 256]);
}

// ---------------- Oja update chunk: one block per (b,h); W streamed once --------
__global__ __launch_bounds__(256) void oja_final_kernel(
    const float* __restrict__ W,
    float* __restrict__ out, int bh0)
{
    const int bh = blockIdx.x + bh0;        // b*H + h
    const int b  = bh >> 3;
    const int h  = bh & 7;

    const float4* __restrict__ W4 = (const float4*)(W   + (size_t)bh * (DHEAD * DHEAD));
    float4* __restrict__       O4 = (float4*)      (out + (size_t)bh * (DHEAD * DHEAD));
    const float* __restrict__ row = g_kvb + (size_t)b * KVBN + h * (2 * DHEAD + 1);

    __shared__ float  s_vs[DHEAD];
    __shared__ float  s_ks[DHEAD];
    __shared__ float  part[16][DHEAD];
    __shared__ float  red[DHEAD];
    __shared__ float  s_lr, s_max, s_sum;

    const int tid = threadIdx.x;
    if (tid < DHEAD) {
        s_ks[tid] = row[tid];
        s_vs[tid] = tanhf(row[DHEAD + tid]);
    }
    if (tid == 0) s_lr = 1.f / (1.f + expf(-row[2 * DHEAD]));
    __syncthreads();

    const int c4 = tid & 15;
    const int dg = tid >> 4;

    float4 wreg[4];
    float p0 = 0.f, p1 = 0.f, p2 = 0.f, p3 = 0.f;
    #pragma unroll
    for (int i = 0; i < 4; i++) {
        int d = dg + 16 * i;
        float4 w = __ldcs(&W4[d * 16 + c4]);
        wreg[i] = w;
        float v = s_vs[d];
        p0 = fmaf(w.x, v, p0);
        p1 = fmaf(w.y, v, p1);
        p2 = fmaf(w.z, v, p2);
        p3 = fmaf(w.w, v, p3);
    }
    part[dg][4 * c4 + 0] = p0;
    part[dg][4 * c4 + 1] = p1;
    part[dg][4 * c4 + 2] = p2;
    part[dg][4 * c4 + 3] = p3;
    __syncthreads();

    if (tid < DHEAD) {
        float rm = 0.f;
        #pragma unroll
        for (int g = 0; g < 16; g++) rm += part[g][tid];
        red[tid] = s_ks[tid] - rm;
    }
    __syncthreads();
    if (tid < 32) {
        float mx = fmaxf(red[tid], red[tid + 32]);
        #pragma unroll
        for (int o = 16; o > 0; o >>= 1) mx = fmaxf(mx, __shfl_xor_sync(0xffffffffu, mx, o));
        if (tid == 0) s_max = mx;
    }
    __syncthreads();
    if (tid < DHEAD) red[tid] = expf(red[tid] - s_max);
    __syncthreads();
    if (tid < 32) {
        float s = red[tid] + red[tid + 32];
        #pragma unroll
        for (int o = 16; o > 0; o >>= 1) s += __shfl_xor_sync(0xffffffffu, s, o);
        if (tid == 0) s_sum = s;
    }
    __syncthreads();
    if (tid < DHEAD) s_ks[tid] = red[tid] * (s_lr / s_sum);
    __syncthreads();

    const float k0 = s_ks[4 * c4 + 0];
    const float k1 = s_ks[4 * c4 + 1];
    const float k2 = s_ks[4 * c4 + 2];
    const float k3 = s_ks[4 * c4 + 3];
    #pragma unroll
    for (int i = 0; i < 4; i++) {
        int d = dg + 16 * i;
        float v = s_vs[d];
        float4 w = wreg[i];
        float4 o;
        o.x = fmaf(v, k0, w.x);
        o.y = fmaf(v, k1, w.y);
        o.z = fmaf(v, k2, w.z);
        o.w = fmaf(v, k3, w.w);
        __stcs(&O4[d * 16 + c4], o);
    }
}

// ---------------- launch: batch-chunk pipeline, Oja on a second stream ----------------
extern "C" void kernel_launch(void* const* d_in, const int* in_sizes, int n_in,
                              void* d_out, int out_size)
{
    const float* x     = (const float*)d_in[0];
    const float* z     = (const float*)d_in[1];
    const float* W     = (const float*)d_in[2];
    const float* ip_w  = (const float*)d_in[3];
    const float* ip_b  = (const float*)d_in[4];
    const float* ln_g  = (const float*)d_in[5];
    const float* ln_b  = (const float*)d_in[6];
    const float* mg_w  = (const float*)d_in[7];
    const float* mg_b  = (const float*)d_in[8];
    const float* kvb_w = (const float*)d_in[9];
    const float* kvb_b = (const float*)d_in[10];
    float* out = (float*)d_out;

    void *p_xh, *p_ipwh, *p_mgwh, *p_kvbwh, *p_h1, *p_hcath, *p_h2h, *p_kvb;
    cudaGetSymbolAddress(&p_xh,    g_xh);
    cudaGetSymbolAddress(&p_ipwh,  g_ipwh);
    cudaGetSymbolAddress(&p_mgwh,  g_mgwh);
    cudaGetSymbolAddress(&p_kvbwh, g_kvbwh);
    cudaGetSymbolAddress(&p_h1,    g_h1);
    cudaGetSymbolAddress(&p_hcath, g_hcath);
    cudaGetSymbolAddress(&p_h2h,   g_h2h);
    cudaGetSymbolAddress(&p_kvb,   g_kvb);

    cudaStream_t s2;
    cudaStreamCreateWithFlags(&s2, cudaStreamNonBlocking);
    cudaEvent_t ev[NCHUNK], evJoin;
    for (int c = 0; c < NCHUNK; c++) cudaEventCreateWithFlags(&ev[c], cudaEventDisableTiming);
    cudaEventCreateWithFlags(&evJoin, cudaEventDisableTiming);

    // 0) one fused f32->f16 conversion pass for x + the three weight matrices
    cvt_half_kernel<<<1184, 256>>>(
        (const float2*)x,     (__half2*)p_xh,    BATCH * INDIM / 2,
        (const float2*)ip_w,  (__half2*)p_ipwh,  INDIM * LATENT / 2,
        (const float2*)mg_w,  (__half2*)p_mgwh,  1024 * LATENT / 2,
        (const float2*)kvb_w, (__half2*)p_kvbwh, LATENT * KVBN / 2);

    for (int c = 0; c < NCHUNK; c++) {
        const size_t r0 = (size_t)c * CROWS;
        // 1) h1 = xh @ ipwh + ip_b  (fp32 out)
        {
            dim3 grid(LATENT / HGBN, CROWS / HGBM);
            h_gemm<false, float><<<grid, 128>>>(CROWS, LATENT, INDIM,
                (const __half*)p_xh + r0 * INDIM, INDIM,
                (const __half*)p_ipwh, LATENT, ip_b,
                (float*)p_h1 + r0 * LATENT, LATENT);
        }
        // 2) LayerNorm -> hcath (fp16) + z concat
        ln_concat_kernel<<<CROWS, 256>>>(z, ln_g, ln_b, (int)r0);
        // 3) h2h = hcath @ mgwh + mg_b  (fp16 out)
        {
            dim3 grid(LATENT / HGBN, CROWS / HGBM);
            h_gemm<false, __half><<<grid, 128>>>(CROWS, LATENT, 1024,
                (const __half*)p_hcath + r0 * 1024, 1024,
                (const __half*)p_mgwh, LATENT, mg_b,
                (__half*)p_h2h + r0 * LATENT, LATENT);
        }
        // 4) kvb = h2h @ kvbwh + kvb_b  (fp32 out, N=1032 bounds)
        {
            dim3 grid((KVBN + HGBN - 1) / HGBN, CROWS / HGBM);
            h_gemm<true, float><<<grid, 128>>>(CROWS, KVBN, LATENT,
                (const __half*)p_h2h + r0 * LATENT, LATENT,
                (const __half*)p_kvbwh, KVBN, kvb_b,
                (float*)p_kvb + r0 * KVBN, KVBN);
        }
        // 5) Oja chunk on second stream, ordered after this chunk's GEMM3
        cudaEventRecord(ev[c], 0);
        cudaStreamWaitEvent(s2, ev[c], 0);
        oja_final_kernel<<<CROWS * NHEAD, 256, 0, s2>>>(W, out, (int)(r0 * NHEAD));
    }
    // join second stream back into the capture/origin stream
    cudaEventRecord(evJoin, s2);
    cudaStreamWaitEvent(0, evJoin, 0);
    // note: streams/events intentionally not destroyed here — they may be
    // referenced by an in-progress graph capture owned by the harness.
}

// round 9
// speedup vs baseline: 1.2130x; 1.2130x over previous
#include <cuda_runtime.h>
#include <cuda_fp16.h>
#include <math.h>
#include <stdint.h>

// Problem constants
#define BATCH   4096
#define INDIM   512
#define LATENT  512
#define NHEAD   8
#define DHEAD   64
#define KVBN    1032            // H*(2D+1) = 8*129
#define LN_EPS  1e-5f
#define NCHUNK  4
#define CROWS   (BATCH / NCHUNK)   // 1024 rows per tail chunk

// ---------------- scratch (device globals; no runtime alloc allowed) ----------------
__device__ __half g_xh   [BATCH * INDIM];
__device__ __half g_ipwh [INDIM * LATENT];
__device__ __half g_mgwh [1024 * LATENT];
__device__ __half g_kvbwh[LATENT * KVBN];
__device__ float  g_h1   [BATCH * LATENT];   // GEMM1 out (fp32, pre-LN)
__device__ __half g_hcath[BATCH * 1024];     // [LN(h) | z] fp16
__device__ __half g_h2h  [BATCH * LATENT];   // GEMM2 out fp16
__device__ float  g_kvb  [BATCH * KVBN];     // GEMM3 out fp32

__device__ __forceinline__ uint32_t smem_u32(const void* p) {
    return (uint32_t)__cvta_generic_to_shared(p);
}
__device__ __forceinline__ void cp_async16(uint32_t dst, const void* src) {
    asm volatile("cp.async.cg.shared.global [%0], [%1], 16;\n" :: "r"(dst), "l"(src));
}
__device__ __forceinline__ void cp_commit() { asm volatile("cp.async.commit_group;\n"); }
__device__ __forceinline__ void cp_wait1()  { asm volatile("cp.async.wait_group 1;\n"); }

__device__ __forceinline__ void ldsm_x4(uint32_t& r0, uint32_t& r1, uint32_t& r2, uint32_t& r3, uint32_t addr) {
    asm volatile("ldmatrix.sync.aligned.m8n8.x4.shared.b16 {%0,%1,%2,%3}, [%4];"
                 : "=r"(r0), "=r"(r1), "=r"(r2), "=r"(r3) : "r"(addr));
}
__device__ __forceinline__ void ldsm_x4_t(uint32_t& r0, uint32_t& r1, uint32_t& r2, uint32_t& r3, uint32_t addr) {
    asm volatile("ldmatrix.sync.aligned.m8n8.x4.trans.shared.b16 {%0,%1,%2,%3}, [%4];"
                 : "=r"(r0), "=r"(r1), "=r"(r2), "=r"(r3) : "r"(addr));
}

// ---------------- f32 -> f16 conversion (two sources per launch) ----------------
__global__ __launch_bounds__(256) void cvt_half2_kernel(
    const float2* __restrict__ s0, __half2* __restrict__ d0, int n0,
    const float2* __restrict__ s1, __half2* __restrict__ d1, int n1)
{
    const int t = blockIdx.x * 256 + threadIdx.x;
    const int stride = gridDim.x * 256;
    for (int i = t; i < n0; i += stride) d0[i] = __float22half2_rn(s0[i]);
    for (int i = t; i < n1; i += stride) d1[i] = __float22half2_rn(s1[i]);
}

// ---------------- fp16 tensor-core GEMM: C = A(MxK) * B(KxN) + bias ----------------
// BM=128, BN=64, BK=32, 128 threads (4 warps: 2 along M x 2 along N), warp tile 64x32.
// m16n8k16 f16 mma, f32 accumulate. 3-stage cp.async ring, ldmatrix fragment loads.
#define HGBM 128
#define HGBN 64
#define HGBK 32
#define SAH  40
#define SBH  72
#define NST  3

template<bool NB, typename OutT>
__global__ __launch_bounds__(128, 4) void h_gemm(
    int M, int N, int K,
    const __half* __restrict__ A, int lda,
    const __half* __restrict__ B, int ldb,
    const float* __restrict__ bias,
    OutT* __restrict__ C, int ldc)
{
    __shared__ __half As[NST][HGBM][SAH];
    __shared__ __half Bs[NST][HGBK][SBH];

    const int tid  = threadIdx.x;
    const int wid  = tid >> 5;
    const int lane = tid & 31;
    const int grp  = lane >> 2;
    const int tig  = lane & 3;
    const int warp_m = (wid & 1) * 64;
    const int warp_n = (wid >> 1) * 32;
    const int block_row = blockIdx.y * HGBM;
    const int block_col = blockIdx.x * HGBN;

    float acc[4][4][4];
    #pragma unroll
    for (int a = 0; a < 4; a++)
        #pragma unroll
        for (int b = 0; b < 4; b++)
            #pragma unroll
            for (int c = 0; c < 4; c++) acc[a][b][c] = 0.f;

    const int KT = K / HGBK;

    auto load_stage = [&](int s, int kt) {
        const int k0 = kt * HGBK;
        #pragma unroll
        for (int i = 0; i < 4; i++) {
            int idx = tid + 128 * i;
            int r = idx >> 2;
            int j = (idx & 3) * 8;
            cp_async16(smem_u32(&As[s][r][j]),
                       A + (size_t)(block_row + r) * lda + k0 + j);
        }
        #pragma unroll
        for (int i = 0; i < 2; i++) {
            int idx = tid + 128 * i;
            int kk = idx >> 3;
            int c8 = (idx & 7) * 8;
            if (!NB || (block_col + c8) < N) {
                cp_async16(smem_u32(&Bs[s][kk][c8]),
                           B + (size_t)(k0 + kk) * ldb + block_col + c8);
            }
        }
    };

    load_stage(0, 0); cp_commit();
    load_stage(1, 1); cp_commit();

    const int a_row = warp_m + (lane & 15);
    const int a_k8  = (lane >> 4) << 3;
    const int b_r16 = (lane & 15);
    const int b_n8  = (lane >> 4) << 3;

    for (int kt = 0; kt < KT; kt++) {
        cp_wait1();
        __syncthreads();
        if (kt + 2 < KT) load_stage((kt + 2) % NST, kt + 2);
        cp_commit();

        const int s = kt % NST;
        #pragma unroll
        for (int ks = 0; ks < 2; ks++) {
            const int k0 = ks * 16;
            uint32_t a[4][4];
            #pragma unroll
            for (int mt = 0; mt < 4; mt++) {
                uint32_t addr = smem_u32(&As[s][a_row + mt * 16][k0 + a_k8]);
                ldsm_x4(a[mt][0], a[mt][1], a[mt][2], a[mt][3], addr);
            }
            uint32_t b[2][4];
            #pragma unroll
            for (int bt = 0; bt < 2; bt++) {
                uint32_t addr = smem_u32(&Bs[s][k0 + b_r16][warp_n + bt * 16 + b_n8]);
                ldsm_x4_t(b[bt][0], b[bt][1], b[bt][2], b[bt][3], addr);
            }
            #pragma unroll
            for (int mt = 0; mt < 4; mt++)
                #pragma unroll
                for (int nt = 0; nt < 4; nt++) {
                    const int bt = nt >> 1;
                    const int hp = (nt & 1) * 2;
                    asm volatile(
                        "mma.sync.aligned.m16n8k16.row.col.f32.f16.f16.f32 "
                        "{%0,%1,%2,%3}, {%4,%5,%6,%7}, {%8,%9}, {%0,%1,%2,%3};\n"
                        : "+f"(acc[mt][nt][0]), "+f"(acc[mt][nt][1]),
                          "+f"(acc[mt][nt][2]), "+f"(acc[mt][nt][3])
                        : "r"(a[mt][0]), "r"(a[mt][1]), "r"(a[mt][2]), "r"(a[mt][3]),
                          "r"(b[bt][hp]), "r"(b[bt][hp + 1]));
                }
        }
    }

    #pragma unroll
    for (int mt = 0; mt < 4; mt++) {
        int r0 = block_row + warp_m + mt * 16 + grp;
        #pragma unroll
        for (int nt = 0; nt < 4; nt++) {
            int c = block_col + warp_n + nt * 8 + tig * 2;
            if (!NB || c < N) {
                float b0 = bias[c], b1 = bias[c + 1];
                float o00 = acc[mt][nt][0] + b0, o01 = acc[mt][nt][1] + b1;
                float o10 = acc[mt][nt][2] + b0, o11 = acc[mt][nt][3] + b1;
                if (sizeof(OutT) == 4) {
                    *(float2*)((float*)C + (size_t)r0 * ldc + c)       = make_float2(o00, o01);
                    *(float2*)((float*)C + (size_t)(r0 + 8) * ldc + c) = make_float2(o10, o11);
                } else {
                    *(__half2*)((__half*)C + (size_t)r0 * ldc + c)       = __floats2half2_rn(o00, o01);
                    *(__half2*)((__half*)C + (size_t)(r0 + 8) * ldc + c) = __floats2half2_rn(o10, o11);
                }
            }
        }
    }
}

// ---------------- LayerNorm (512) on g_h1 -> g_hcath (fp16) + z concat ----------------
__global__ __launch_bounds__(256) void ln_concat_kernel(
    const float* __restrict__ z, const float* __restrict__ gamma,
    const float* __restrict__ beta)
{
    const int b = blockIdx.x;
    const float* row = g_h1 + (size_t)b * LATENT;
    const float* zr  = z + (size_t)b * LATENT;
    __half* oh = g_hcath + (size_t)b * 1024;
    const int tid = threadIdx.x;

    float v0 = row[tid];
    float v1 = row[tid + 256];

    __shared__ float red[256];
    red[tid] = v0 + v1;
    __syncthreads();
    #pragma unroll
    for (int s = 128; s > 0; s >>= 1) {
        if (tid < s) red[tid] += red[tid + s];
        __syncthreads();
    }
    const float mu = red[0] * (1.f / 512.f);
    __syncthreads();

    float d0 = v0 - mu, d1 = v1 - mu;
    red[tid] = d0 * d0 + d1 * d1;
    __syncthreads();
    #pragma unroll
    for (int s = 128; s > 0; s >>= 1) {
        if (tid < s) red[tid] += red[tid + s];
        __syncthreads();
    }
    const float var = red[0] * (1.f / 512.f);
    const float inv = rsqrtf(var + LN_EPS);

    oh[tid]       = __float2half(d0 * inv * gamma[tid]       + beta[tid]);
    oh[tid + 256] = __float2half(d1 * inv * gamma[tid + 256] + beta[tid + 256]);
    oh[512 + tid]       = __float2half(zr[tid]);
    oh[512 + tid + 256] = __float2half(zr[tid + 256]);
}

// ---------------- Oja update chunk: one block per (b,h); W streamed once --------
__global__ __launch_bounds__(256) void oja_final_kernel(
    const float* __restrict__ W,
    float* __restrict__ out, int bh0)
{
    const int bh = blockIdx.x + bh0;        // b*H + h
    const int b  = bh >> 3;
    const int h  = bh & 7;

    const float4* __restrict__ W4 = (const float4*)(W   + (size_t)bh * (DHEAD * DHEAD));
    float4* __restrict__       O4 = (float4*)      (out + (size_t)bh * (DHEAD * DHEAD));
    const float* __restrict__ row = g_kvb + (size_t)b * KVBN + h * (2 * DHEAD + 1);

    __shared__ float  s_vs[DHEAD];
    __shared__ float  s_ks[DHEAD];
    __shared__ float  part[16][DHEAD];
    __shared__ float  red[DHEAD];
    __shared__ float  s_lr, s_max, s_sum;

    const int tid = threadIdx.x;
    if (tid < DHEAD) {
        s_ks[tid] = row[tid];
        s_vs[tid] = tanhf(row[DHEAD + tid]);
    }
    if (tid == 0) s_lr = 1.f / (1.f + expf(-row[2 * DHEAD]));
    __syncthreads();

    const int c4 = tid & 15;
    const int dg = tid >> 4;

    float4 wreg[4];
    float p0 = 0.f, p1 = 0.f, p2 = 0.f, p3 = 0.f;
    #pragma unroll
    for (int i = 0; i < 4; i++) {
        int d = dg + 16 * i;
        float4 w = __ldcs(&W4[d * 16 + c4]);
        wreg[i] = w;
        float v = s_vs[d];
        p0 = fmaf(w.x, v, p0);
        p1 = fmaf(w.y, v, p1);
        p2 = fmaf(w.z, v, p2);
        p3 = fmaf(w.w, v, p3);
    }
    part[dg][4 * c4 + 0] = p0;
    part[dg][4 * c4 + 1] = p1;
    part[dg][4 * c4 + 2] = p2;
    part[dg][4 * c4 + 3] = p3;
    __syncthreads();

    if (tid < DHEAD) {
        float rm = 0.f;
        #pragma unroll
        for (int g = 0; g < 16; g++) rm += part[g][tid];
        red[tid] = s_ks[tid] - rm;
    }
    __syncthreads();
    if (tid < 32) {
        float mx = fmaxf(red[tid], red[tid + 32]);
        #pragma unroll
        for (int o = 16; o > 0; o >>= 1) mx = fmaxf(mx, __shfl_xor_sync(0xffffffffu, mx, o));
        if (tid == 0) s_max = mx;
    }
    __syncthreads();
    if (tid < DHEAD) red[tid] = expf(red[tid] - s_max);
    __syncthreads();
    if (tid < 32) {
        float s = red[tid] + red[tid + 32];
        #pragma unroll
        for (int o = 16; o > 0; o >>= 1) s += __shfl_xor_sync(0xffffffffu, s, o);
        if (tid == 0) s_sum = s;
    }
    __syncthreads();
    if (tid < DHEAD) s_ks[tid] = red[tid] * (s_lr / s_sum);
    __syncthreads();

    const float k0 = s_ks[4 * c4 + 0];
    const float k1 = s_ks[4 * c4 + 1];
    const float k2 = s_ks[4 * c4 + 2];
    const float k3 = s_ks[4 * c4 + 3];
    #pragma unroll
    for (int i = 0; i < 4; i++) {
        int d = dg + 16 * i;
        float v = s_vs[d];
        float4 w = wreg[i];
        float4 o;
        o.x = fmaf(v, k0, w.x);
        o.y = fmaf(v, k1, w.y);
        o.z = fmaf(v, k2, w.z);
        o.w = fmaf(v, k3, w.w);
        __stcs(&O4[d * 16 + c4], o);
    }
}

// ---------------- launch: monolithic GEMM chain; overlap cvt_b and the Oja tail ----------------
extern "C" void kernel_launch(void* const* d_in, const int* in_sizes, int n_in,
                              void* d_out, int out_size)
{
    const float* x     = (const float*)d_in[0];
    const float* z     = (const float*)d_in[1];
    const float* W     = (const float*)d_in[2];
    const float* ip_w  = (const float*)d_in[3];
    const float* ip_b  = (const float*)d_in[4];
    const float* ln_g  = (const float*)d_in[5];
    const float* ln_b  = (const float*)d_in[6];
    const float* mg_w  = (const float*)d_in[7];
    const float* mg_b  = (const float*)d_in[8];
    const float* kvb_w = (const float*)d_in[9];
    const float* kvb_b = (const float*)d_in[10];
    float* out = (float*)d_out;

    void *p_xh, *p_ipwh, *p_mgwh, *p_kvbwh, *p_h1, *p_hcath, *p_h2h, *p_kvb;
    cudaGetSymbolAddress(&p_xh,    g_xh);
    cudaGetSymbolAddress(&p_ipwh,  g_ipwh);
    cudaGetSymbolAddress(&p_mgwh,  g_mgwh);
    cudaGetSymbolAddress(&p_kvbwh, g_kvbwh);
    cudaGetSymbolAddress(&p_h1,    g_h1);
    cudaGetSymbolAddress(&p_hcath, g_hcath);
    cudaGetSymbolAddress(&p_h2h,   g_h2h);
    cudaGetSymbolAddress(&p_kvb,   g_kvb);

    cudaStream_t s2;
    cudaStreamCreateWithFlags(&s2, cudaStreamNonBlocking);
    cudaEvent_t evFork, evCvtB, ev[NCHUNK], evJoin;
    cudaEventCreateWithFlags(&evFork, cudaEventDisableTiming);
    cudaEventCreateWithFlags(&evCvtB, cudaEventDisableTiming);
    for (int c = 0; c < NCHUNK; c++) cudaEventCreateWithFlags(&ev[c], cudaEventDisableTiming);
    cudaEventCreateWithFlags(&evJoin, cudaEventDisableTiming);

    // fork stream2 off the capture stream
    cudaEventRecord(evFork, 0);
    cudaStreamWaitEvent(s2, evFork, 0);

    // 0a) convert x + ip_w (needed by GEMM1) on the main stream
    cvt_half2_kernel<<<600, 256>>>(
        (const float2*)x,    (__half2*)p_xh,   BATCH * INDIM / 2,
        (const float2*)ip_w, (__half2*)p_ipwh, INDIM * LATENT / 2);
    // 0b) convert mg_w + kvb_w on stream2, overlapped with GEMM1 + LN
    cvt_half2_kernel<<<600, 256, 0, s2>>>(
        (const float2*)mg_w,  (__half2*)p_mgwh,  1024 * LATENT / 2,
        (const float2*)kvb_w, (__half2*)p_kvbwh, LATENT * KVBN / 2);
    cudaEventRecord(evCvtB, s2);

    // 1) h1 = xh @ ipwh + ip_b  (fp32 out, full batch)
    {
        dim3 grid(LATENT / HGBN, BATCH / HGBM);
        h_gemm<false, float><<<grid, 128>>>(BATCH, LATENT, INDIM,
            (const __half*)p_xh, INDIM, (const __half*)p_ipwh, LATENT, ip_b,
            (float*)p_h1, LATENT);
    }
    // 2) LayerNorm -> hcath (fp16) + z concat (full batch)
    ln_concat_kernel<<<BATCH, 256>>>(z, ln_g, ln_b);

    // wait for cvt_b before GEMM2
    cudaStreamWaitEvent(0, evCvtB, 0);

    // 3) h2h = hcath @ mgwh + mg_b  (fp16 out, full batch)
    {
        dim3 grid(LATENT / HGBN, BATCH / HGBM);
        h_gemm<false, __half><<<grid, 128>>>(BATCH, LATENT, 1024,
            (const __half*)p_hcath, 1024, (const __half*)p_mgwh, LATENT, mg_b,
            (__half*)p_h2h, LATENT);
    }

    // 4+5) tail pipeline: GEMM3 chunk on main stream, Oja chunk forked to stream2
    for (int c = 0; c < NCHUNK; c++) {
        const size_t r0 = (size_t)c * CROWS;
        {
            dim3 grid((KVBN + HGBN - 1) / HGBN, CROWS / HGBM);
            h_gemm<true, float><<<grid, 128>>>(CROWS, KVBN, LATENT,
                (const __half*)p_h2h + r0 * LATENT, LATENT,
                (const __half*)p_kvbwh, KVBN, kvb_b,
                (float*)p_kvb + r0 * KVBN, KVBN);
        }
        cudaEventRecord(ev[c], 0);
        cudaStreamWaitEvent(s2, ev[c], 0);
        oja_final_kernel<<<CROWS * NHEAD, 256, 0, s2>>>(W, out, (int)(r0 * NHEAD));
    }

    // join stream2 back into the capture stream
    cudaEventRecord(evJoin, s2);
    cudaStreamWaitEvent(0, evJoin, 0);
    // streams/events intentionally not destroyed — graph capture may reference them.
}